// round 13
// baseline (speedup 1.0000x reference)
#include <cuda_runtime.h>
#include <cuda_fp16.h>
#include <math.h>
#include <stdint.h>

#define BATCH 2
#define SEQ   2048
#define DIN   1024
#define DOUT  1024
#define NH    16
#define HD    64
#define MTOT  (BATCH*SEQ)   // 4096

// ---------------------------------------------------------------------------
// scratch (no cudaMalloc allowed)
// ---------------------------------------------------------------------------
__device__ __half g_Xh[MTOT*DIN];            // x in fp16
__device__ __half g_Wth[4][DIN*DOUT];        // W^T [n][k] fp16 (q,k,v,out)
__device__ __half g_Qh[MTOT*DOUT];           // pre-scaled by 0.125*log2(e)
__device__ __half g_Kh[MTOT*DOUT];
__device__ __half g_Vth[BATCH*NH*HD*SEQ];    // V transposed [b,h,d,s]
__device__ __half g_Ah[MTOT*DOUT];           // attention output

// ---------------------------------------------------------------------------
// helpers
// ---------------------------------------------------------------------------
__device__ __forceinline__ uint32_t smem_u32(const void* p) {
    return (uint32_t)__cvta_generic_to_shared(p);
}

__device__ __forceinline__ void cp_async16(uint32_t dst, const void* src) {
    asm volatile("cp.async.cg.shared.global [%0], [%1], 16;" :: "r"(dst), "l"(src) : "memory");
}
__device__ __forceinline__ void cp_commit() {
    asm volatile("cp.async.commit_group;" ::: "memory");
}
template<int N>
__device__ __forceinline__ void cp_wait() {
    asm volatile("cp.async.wait_group %0;" :: "n"(N) : "memory");
}

__device__ __forceinline__ uint32_t packh2(float a, float b) {
    __half2 h = __floats2half2_rn(a, b);
    return *(uint32_t*)&h;
}

__device__ __forceinline__ uint32_t ex2h2(uint32_t x) {
    uint32_t y; asm("ex2.approx.f16x2 %0, %1;" : "=r"(y) : "r"(x)); return y;
}

// m16n8k16 fp16 HMMA, row.col, fp32 accumulate
__device__ __forceinline__ void mma_f16(float* d, const uint32_t* a, const uint32_t* b) {
    asm volatile(
        "mma.sync.aligned.m16n8k16.row.col.f32.f16.f16.f32 "
        "{%0,%1,%2,%3}, {%4,%5,%6,%7}, {%8,%9}, {%0,%1,%2,%3};"
        : "+f"(d[0]), "+f"(d[1]), "+f"(d[2]), "+f"(d[3])
        : "r"(a[0]), "r"(a[1]), "r"(a[2]), "r"(a[3]), "r"(b[0]), "r"(b[1]));
}

__device__ __forceinline__ void ldsm_x4(uint32_t* r, uint32_t addr) {
    asm volatile("ldmatrix.sync.aligned.m8n8.x4.shared.b16 {%0,%1,%2,%3}, [%4];"
        : "=r"(r[0]), "=r"(r[1]), "=r"(r[2]), "=r"(r[3]) : "r"(addr));
}

// ---------------------------------------------------------------------------
// prep kernel: z<4 -> transpose+convert W[z]; z==4 -> convert x.
// ---------------------------------------------------------------------------
__global__ void prep_kernel(const float* __restrict__ x,
                            const float* __restrict__ Wq,
                            const float* __restrict__ Wk,
                            const float* __restrict__ Wv,
                            const float* __restrict__ Wo) {
    const int z = blockIdx.z;
    const int tx = threadIdx.x, ty = threadIdx.y;
    if (z == 4) {
        const int bid = blockIdx.y * 32 + blockIdx.x;
        const int tid = ty * 32 + tx;
        #pragma unroll
        for (int i = 0; i < 4; i++) {
            int idx = bid * 1024 + i * 256 + tid;
            float4 v = ((const float4*)x)[idx];
            __half2 h0 = __floats2half2_rn(v.x, v.y);
            __half2 h1 = __floats2half2_rn(v.z, v.w);
            uint2 u;
            u.x = *(uint32_t*)&h0;
            u.y = *(uint32_t*)&h1;
            ((uint2*)g_Xh)[idx] = u;
        }
        return;
    }
    __shared__ float t[32][33];
    const float* W = (z == 0) ? Wq : (z == 1) ? Wk : (z == 2) ? Wv : Wo;
    __half* out = g_Wth[z];
    const int n0 = blockIdx.x * 32, k0 = blockIdx.y * 32;
    #pragma unroll
    for (int i = 0; i < 4; i++)
        t[ty + 8*i][tx] = W[(size_t)(k0 + ty + 8*i) * DOUT + n0 + tx];
    __syncthreads();
    #pragma unroll
    for (int i = 0; i < 4; i++)
        out[(size_t)(n0 + ty + 8*i) * DIN + k0 + tx] = __float2half_rn(t[tx][ty + 8*i]);
}

// ---------------------------------------------------------------------------
// fp16 HMMA GEMM: 256x128 CTA tile, warp tile 64x64, BK=128.
// 2-stage cp.async double buffer, ONE __syncthreads per chunk (8 chunks),
// register double-buffered ldmatrix fragments.
// ---------------------------------------------------------------------------
#define HST 136                           // halves per row (128 data + 8 pad)
#define A_STG (256*HST)
#define B_STG (128*HST)
#define GEMM_SMEM (2*(A_STG+B_STG)*2)     // 208896 bytes (1 CTA/SM)

__device__ __forceinline__ void g_load_stage(const __half* __restrict__ A,
                                             const __half* __restrict__ Bt,
                                             uint32_t sA, uint32_t sB,
                                             int slot, int kc, int bm, int bn, int tid) {
    const __half* srcA = A  + (size_t)bm * DIN + kc * 128;
    const __half* srcB = Bt + (size_t)bn * DIN + kc * 128;
    const uint32_t dA = sA + slot * A_STG * 2;
    const uint32_t dB = sB + slot * B_STG * 2;
    #pragma unroll
    for (int i = 0; i < 16; i++) {      // A: 256 rows x 16 chunks of 16B
        int idx = tid + i * 256;
        int row = idx >> 4, c16 = idx & 15;
        cp_async16(dA + (row * HST + c16 * 8) * 2, srcA + (size_t)row * DIN + c16 * 8);
    }
    #pragma unroll
    for (int i = 0; i < 8; i++) {       // B: 128 rows x 16 chunks
        int idx = tid + i * 256;
        int row = idx >> 4, c16 = idx & 15;
        cp_async16(dB + (row * HST + c16 * 8) * 2, srcB + (size_t)row * DIN + c16 * 8);
    }
}

template<int EPI>
__device__ __forceinline__ void gemm_tile_body(const __half* __restrict__ A,
                                               const __half* __restrict__ Bt,
                                               void* __restrict__ Cv, float escale) {
    extern __shared__ __half hsmem[];
    const uint32_t sAu = smem_u32(hsmem);
    const uint32_t sBu = sAu + 2 * A_STG * 2;

    const int tid  = threadIdx.x;
    const int lane = tid & 31;
    const int wid  = tid >> 5;
    const int wm   = wid >> 1;
    const int wn   = wid & 1;
    const int bm   = blockIdx.y * 256;
    const int bn   = blockIdx.x * 128;
    const int gr   = lane >> 2;
    const int c2   = (lane & 3) * 2;

    const int lA_row = lane & 15;
    const int lA_col = (lane >> 4) * 8;
    const int lB_row = (lane & 7) + ((lane >> 4) & 1) * 8;
    const int lB_col = ((lane >> 3) & 1) * 8;

    float acc[32][4] = {};

    const int NKC = DIN / 128;    // 8 chunks

    g_load_stage(A, Bt, sAu, sBu, 0, 0, bm, bn, tid); cp_commit();

    for (int kc = 0; kc < NKC; kc++) {
        cp_wait<0>();                    // chunk kc resident (locally)
        __syncthreads();                 // visible; all warps done with kc-1
        if (kc + 1 < NKC)
            g_load_stage(A, Bt, sAu, sBu, (kc + 1) & 1, kc + 1, bm, bn, tid);
        cp_commit();                     // overlaps with compute of kc

        const uint32_t cA = sAu + (kc & 1) * A_STG * 2;
        const uint32_t cB = sBu + (kc & 1) * B_STG * 2;

        // register double-buffered fragments, 8 k-groups of 16
        uint32_t a[2][4][4], b[2][4][4];
        #pragma unroll
        for (int mi = 0; mi < 4; mi++)
            ldsm_x4(a[0][mi], cA + (((wm * 64 + mi * 16 + lA_row) * HST + lA_col) << 1));
        #pragma unroll
        for (int jj = 0; jj < 4; jj++)
            ldsm_x4(b[0][jj], cB + (((wn * 64 + jj * 16 + lB_row) * HST + lB_col) << 1));

        #pragma unroll
        for (int ks = 0; ks < 8; ks++) {
            const int cb = ks & 1, nb = cb ^ 1;
            if (ks < 7) {
                const int k1 = (ks + 1) * 16;
                #pragma unroll
                for (int mi = 0; mi < 4; mi++)
                    ldsm_x4(a[nb][mi], cA + (((wm * 64 + mi * 16 + lA_row) * HST + k1 + lA_col) << 1));
                #pragma unroll
                for (int jj = 0; jj < 4; jj++)
                    ldsm_x4(b[nb][jj], cB + (((wn * 64 + jj * 16 + lB_row) * HST + k1 + lB_col) << 1));
            }
            #pragma unroll
            for (int mi = 0; mi < 4; mi++)
                #pragma unroll
                for (int j = 0; j < 8; j++)
                    mma_f16(acc[mi*8+j], a[cb][mi], &b[cb][j >> 1][(j & 1) * 2]);
        }
    }

    #pragma unroll
    for (int mi = 0; mi < 4; mi++) {
        const int row = bm + wm * 64 + mi * 16 + gr;
        #pragma unroll
        for (int j = 0; j < 8; j++) {
            const int col = bn + wn * 64 + j * 8 + c2;
            float v0 = acc[mi*8+j][0], v1 = acc[mi*8+j][1];
            float v2 = acc[mi*8+j][2], v3 = acc[mi*8+j][3];
            if (EPI == 0) {
                float* C = (float*)Cv;
                *(float2*)(C + (size_t)row * DOUT + col)       = make_float2(v0, v1);
                *(float2*)(C + (size_t)(row + 8) * DOUT + col) = make_float2(v2, v3);
            } else if (EPI == 1) {
                __half* C = (__half*)Cv;
                *(__half2*)(C + (size_t)row * DOUT + col)       = __floats2half2_rn(v0*escale, v1*escale);
                *(__half2*)(C + (size_t)(row + 8) * DOUT + col) = __floats2half2_rn(v2*escale, v3*escale);
            } else {
                __half* C = (__half*)Cv;
                const int b0i = row >> 11,     s0 = row & 2047;
                const int b1i = (row+8) >> 11, s1 = (row+8) & 2047;
                #pragma unroll
                for (int q = 0; q < 2; q++) {
                    const int cc = col + q;
                    const size_t base = ((size_t)(cc >> 6) * HD + (cc & 63)) * SEQ;
                    C[(size_t)b0i * NH * HD * SEQ + base + s0] = __float2half_rn(q ? v1 : v0);
                    C[(size_t)b1i * NH * HD * SEQ + base + s1] = __float2half_rn(q ? v3 : v2);
                }
            }
        }
    }
}

#define QSCALE (0.125f * 1.4426950408889634f)   // 1/sqrt(64) * log2(e)

__global__ void __launch_bounds__(256) qkv_mma_kernel() {
    if (blockIdx.z == 0)      gemm_tile_body<1>(g_Xh, g_Wth[0], g_Qh, QSCALE);
    else if (blockIdx.z == 1) gemm_tile_body<1>(g_Xh, g_Wth[1], g_Kh, 1.0f);
    else                      gemm_tile_body<2>(g_Xh, g_Wth[2], g_Vth, 1.0f);
}

__global__ void __launch_bounds__(256) out_mma_kernel(float* __restrict__ out) {
    gemm_tile_body<0>(g_Ah, g_Wth[3], out, 1.0f);
}

// ---------------------------------------------------------------------------
// fp16 tensor-core causal flash attention (unchanged from R11/R12):
// fixed-reference base-2 softmax, fp16x2 exp, l via ones-rows MMA,
// paired q-tiles, 3-stage cp.async K/V ring.
// ---------------------------------------------------------------------------
#define HSTA 72
#define KBUF_K (64*HSTA)
#define KBUF_V (80*HSTA)
#define ATTN_SMEM ((3*KBUF_K + 3*KBUF_V)*2)   // 62208 bytes

__device__ __forceinline__ void attn_load(const __half* __restrict__ Kg,
                                          const __half* __restrict__ Vt,
                                          uint32_t sKu, uint32_t sVu,
                                          int slot, int kbase, int tid) {
    const uint32_t dK = sKu + slot * KBUF_K * 2;
    const uint32_t dV = sVu + slot * KBUF_V * 2;
    #pragma unroll
    for (int i = 0; i < 2; i++) {
        int idx = tid + i * 256;
        int row = idx >> 3, c8 = idx & 7;
        uint32_t off = (row * HSTA + c8 * 8) * 2;
        cp_async16(dK + off, Kg + (size_t)(kbase + row) * DOUT + c8 * 8);
        cp_async16(dV + off, Vt + (size_t)row * SEQ + kbase + c8 * 8);
    }
}

__global__ void __launch_bounds__(256, 2) attn_f16_kernel() {
    extern __shared__ __half hsmem[];
    const uint32_t sKu = smem_u32(hsmem);
    const uint32_t sVu = sKu + 3 * KBUF_K * 2;

    const int h   = blockIdx.y;
    const int b   = blockIdx.z;
    const int tid = threadIdx.x;
    const int lane = tid & 31;
    const int wid  = tid >> 5;
    const int gr = lane >> 2, c2 = (lane & 3) * 2;

    const int lB_row = (lane & 7) + ((lane >> 4) & 1) * 8;
    const int lB_col = ((lane >> 3) & 1) * 8;

    const size_t rowbase = (size_t)b * SEQ;
    const int colbase = h * HD;
    const __half* Kg = g_Kh + rowbase * DOUT + colbase;
    const __half* Vt = g_Vth + (size_t)(b * NH + h) * HD * SEQ;

    const int wrow = wid * 16;

    // init constant rows 64-79 of each V slot: rows 64-71 = 1.0, 72-79 = 0.
    for (int i = tid; i < 3 * 16 * (HSTA/2); i += 256) {
        const int slot = i / (16 * (HSTA/2));
        const int rem  = i % (16 * (HSTA/2));
        const int r = rem / (HSTA/2), c = rem % (HSTA/2);
        uint32_t val = (r < 8) ? 0x3C003C00u : 0u;
        *(uint32_t*)(hsmem + 3*KBUF_K + slot*KBUF_V + (64 + r)*HSTA + c*2) = val;
    }

    #pragma unroll
    for (int seg = 0; seg < 2; seg++) {
        const int qt = seg == 0 ? (15 - (int)blockIdx.x) : (int)blockIdx.x;
        const int qbase = qt * 128;
        const int nkb = 2 * qt + 2;
        const int qg0 = qbase + wrow + gr;
        const int qg1 = qg0 + 8;

        // preload Q fragments (already scaled by 0.125*log2e)
        uint32_t qf[4][4];
        {
            const __half* Qg = g_Qh + (rowbase + qbase + wrow + gr) * DOUT + colbase + c2;
            #pragma unroll
            for (int ks = 0; ks < 4; ks++) {
                const __half* qp = Qg + ks * 16;
                qf[ks][0] = *(const uint32_t*)(qp);
                qf[ks][1] = *(const uint32_t*)(qp + 8 * DOUT);
                qf[ks][2] = *(const uint32_t*)(qp + 8);
                qf[ks][3] = *(const uint32_t*)(qp + 8 * DOUT + 8);
            }
        }

        float o[9][4] = {};   // o[0..7] = output dims; o[8] = row-sum l

        __syncthreads();
        attn_load(Kg, Vt, sKu, sVu, 0, 0, tid); cp_commit();
        attn_load(Kg, Vt, sKu, sVu, 1, 64, tid); cp_commit();

        for (int kb = 0; kb < nkb; kb++) {
            cp_wait<1>();
            __syncthreads();
            if (kb + 2 < nkb)
                attn_load(Kg, Vt, sKu, sVu, (kb + 2) % 3, (kb + 2) * 64, tid);
            cp_commit();

            const uint32_t cK = sKu + (kb % 3) * KBUF_K * 2;
            const uint32_t cV = sVu + (kb % 3) * KBUF_V * 2;
            const int kbase = kb * 64;

            // S = Q K^T  (base-2 log scale)
            float s[8][4] = {};
            #pragma unroll
            for (int ks = 0; ks < 4; ks++) {
                const int k0 = ks * 16;
                uint32_t bk[4][4];
                #pragma unroll
                for (int jj = 0; jj < 4; jj++)
                    ldsm_x4(bk[jj], cK + (((jj * 16 + lB_row) * HSTA + k0 + lB_col) << 1));
                #pragma unroll
                for (int j = 0; j < 8; j++)
                    mma_f16(s[j], qf[ks], &bk[j >> 1][(j & 1) * 2]);
            }

            // causal mask only near the diagonal
            if (kbase + 63 > qbase + wrow) {
                #pragma unroll
                for (int j = 0; j < 8; j++) {
                    const int col0 = kbase + j * 8 + c2;
                    if (col0     > qg0) s[j][0] = -64.f;
                    if (col0 + 1 > qg0) s[j][1] = -64.f;
                    if (col0     > qg1) s[j][2] = -64.f;
                    if (col0 + 1 > qg1) s[j][3] = -64.f;
                }
            }

            // P = exp2(s) in fp16x2, directly in A-fragment order
            uint32_t pf[8][2];
            #pragma unroll
            for (int j = 0; j < 8; j++) {
                pf[j][0] = ex2h2(packh2(s[j][0], s[j][1]));
                pf[j][1] = ex2h2(packh2(s[j][2], s[j][3]));
            }

            // O += P V ; extra n-tile (ones rows) accumulates l into o[8]
            #pragma unroll
            for (int t = 0; t < 4; t++) {
                const int k0 = t * 16;
                uint32_t ap[4] = { pf[2*t][0], pf[2*t][1], pf[2*t+1][0], pf[2*t+1][1] };
                uint32_t bv[5][4];
                #pragma unroll
                for (int jj = 0; jj < 5; jj++)
                    ldsm_x4(bv[jj], cV + (((jj * 16 + lB_row) * HSTA + k0 + lB_col) << 1));
                #pragma unroll
                for (int j = 0; j < 9; j++)
                    mma_f16(o[j], ap, &bv[j >> 1][(j & 1) * 2]);
            }
        }

        // normalize by l + fp16 store
        const float inv0 = 1.f / o[8][0];
        const float inv1 = 1.f / o[8][2];
        #pragma unroll
        for (int j = 0; j < 8; j++) {
            const int col = colbase + j * 8 + c2;
            *(__half2*)&g_Ah[(rowbase + qbase + wrow + gr) * DOUT + col] =
                __floats2half2_rn(o[j][0] * inv0, o[j][1] * inv0);
            *(__half2*)&g_Ah[(rowbase + qbase + wrow + gr + 8) * DOUT + col] =
                __floats2half2_rn(o[j][2] * inv1, o[j][3] * inv1);
        }
    }
}

// ---------------------------------------------------------------------------
extern "C" void kernel_launch(void* const* d_in, const int* in_sizes, int n_in,
                              void* d_out, int out_size) {
    (void)in_sizes; (void)n_in; (void)out_size;
    const float* x    = (const float*)d_in[0];
    const float* Wq   = (const float*)d_in[1];
    const float* Wk   = (const float*)d_in[2];
    const float* Wv   = (const float*)d_in[3];
    const float* Wout = (const float*)d_in[4];
    float* out = (float*)d_out;

    static bool attr_set = false;
    if (!attr_set) {
        cudaFuncSetAttribute(attn_f16_kernel,
                             cudaFuncAttributeMaxDynamicSharedMemorySize, ATTN_SMEM);
        cudaFuncSetAttribute(qkv_mma_kernel,
                             cudaFuncAttributeMaxDynamicSharedMemorySize, GEMM_SMEM);
        cudaFuncSetAttribute(out_mma_kernel,
                             cudaFuncAttributeMaxDynamicSharedMemorySize, GEMM_SMEM);
        attr_set = true;
    }

    prep_kernel<<<dim3(32, 32, 5), dim3(32, 8)>>>(x, Wq, Wk, Wv, Wout);

    qkv_mma_kernel<<<dim3(DOUT/128, MTOT/256, 3), 256, GEMM_SMEM>>>();

    attn_f16_kernel<<<dim3(SEQ/256, NH, BATCH), 256, ATTN_SMEM>>>();

    out_mma_kernel<<<dim3(DOUT/128, MTOT/256), 256, GEMM_SMEM>>>(out);
}

// round 14
// speedup vs baseline: 1.0372x; 1.0372x over previous
#include <cuda_runtime.h>
#include <cuda_fp16.h>
#include <math.h>
#include <stdint.h>

#define BATCH 2
#define SEQ   2048
#define DIN   1024
#define DOUT  1024
#define NH    16
#define HD    64
#define MTOT  (BATCH*SEQ)   // 4096

// ---------------------------------------------------------------------------
// scratch (no cudaMalloc allowed)
// ---------------------------------------------------------------------------
__device__ __half g_Xh[MTOT*DIN];            // x in fp16
__device__ __half g_Wth[4][DIN*DOUT];        // W^T [n][k] fp16 (q,k,v,out)
__device__ __half g_Qh[MTOT*DOUT];           // pre-scaled by 0.125*log2(e)
__device__ __half g_Kh[MTOT*DOUT];
__device__ __half g_Vth[BATCH*NH*HD*SEQ];    // V transposed [b,h,d,s]
__device__ __half g_Ah[MTOT*DOUT];           // attention output

// ---------------------------------------------------------------------------
// helpers
// ---------------------------------------------------------------------------
__device__ __forceinline__ uint32_t smem_u32(const void* p) {
    return (uint32_t)__cvta_generic_to_shared(p);
}

__device__ __forceinline__ void cp_async16(uint32_t dst, const void* src) {
    asm volatile("cp.async.cg.shared.global [%0], [%1], 16;" :: "r"(dst), "l"(src) : "memory");
}
__device__ __forceinline__ void cp_commit() {
    asm volatile("cp.async.commit_group;" ::: "memory");
}
template<int N>
__device__ __forceinline__ void cp_wait() {
    asm volatile("cp.async.wait_group %0;" :: "n"(N) : "memory");
}

__device__ __forceinline__ uint32_t packh2(float a, float b) {
    __half2 h = __floats2half2_rn(a, b);
    return *(uint32_t*)&h;
}

__device__ __forceinline__ uint32_t ex2h2(uint32_t x) {
    uint32_t y; asm("ex2.approx.f16x2 %0, %1;" : "=r"(y) : "r"(x)); return y;
}

// m16n8k16 fp16 HMMA, row.col, fp32 accumulate
__device__ __forceinline__ void mma_f16(float* d, const uint32_t* a, const uint32_t* b) {
    asm volatile(
        "mma.sync.aligned.m16n8k16.row.col.f32.f16.f16.f32 "
        "{%0,%1,%2,%3}, {%4,%5,%6,%7}, {%8,%9}, {%0,%1,%2,%3};"
        : "+f"(d[0]), "+f"(d[1]), "+f"(d[2]), "+f"(d[3])
        : "r"(a[0]), "r"(a[1]), "r"(a[2]), "r"(a[3]), "r"(b[0]), "r"(b[1]));
}

__device__ __forceinline__ void ldsm_x4(uint32_t* r, uint32_t addr) {
    asm volatile("ldmatrix.sync.aligned.m8n8.x4.shared.b16 {%0,%1,%2,%3}, [%4];"
        : "=r"(r[0]), "=r"(r[1]), "=r"(r[2]), "=r"(r[3]) : "r"(addr));
}

// ---------------------------------------------------------------------------
// prep kernel: z<4 -> transpose+convert W[z]; z==4 -> convert x.
// ---------------------------------------------------------------------------
__global__ void prep_kernel(const float* __restrict__ x,
                            const float* __restrict__ Wq,
                            const float* __restrict__ Wk,
                            const float* __restrict__ Wv,
                            const float* __restrict__ Wo) {
    const int z = blockIdx.z;
    const int tx = threadIdx.x, ty = threadIdx.y;
    if (z == 4) {
        const int bid = blockIdx.y * 32 + blockIdx.x;
        const int tid = ty * 32 + tx;
        #pragma unroll
        for (int i = 0; i < 4; i++) {
            int idx = bid * 1024 + i * 256 + tid;
            float4 v = ((const float4*)x)[idx];
            __half2 h0 = __floats2half2_rn(v.x, v.y);
            __half2 h1 = __floats2half2_rn(v.z, v.w);
            uint2 u;
            u.x = *(uint32_t*)&h0;
            u.y = *(uint32_t*)&h1;
            ((uint2*)g_Xh)[idx] = u;
        }
        return;
    }
    __shared__ float t[32][33];
    const float* W = (z == 0) ? Wq : (z == 1) ? Wk : (z == 2) ? Wv : Wo;
    __half* out = g_Wth[z];
    const int n0 = blockIdx.x * 32, k0 = blockIdx.y * 32;
    #pragma unroll
    for (int i = 0; i < 4; i++)
        t[ty + 8*i][tx] = W[(size_t)(k0 + ty + 8*i) * DOUT + n0 + tx];
    __syncthreads();
    #pragma unroll
    for (int i = 0; i < 4; i++)
        out[(size_t)(n0 + ty + 8*i) * DIN + k0 + tx] = __float2half_rn(t[tx][ty + 8*i]);
}

// ---------------------------------------------------------------------------
// fp16 HMMA GEMM (R12 config, best validated): 256x128 CTA tile, warp tile
// 64x64, BK=64, 4-stage cp.async pipeline, one __syncthreads per chunk,
// register double-buffered ldmatrix fragments.
// ---------------------------------------------------------------------------
#define HST 72
#define A_STG (256*HST)
#define B_STG (128*HST)
#define GSTAGES 4
#define GEMM_SMEM (GSTAGES*(A_STG+B_STG)*2)   // 221184 bytes

__device__ __forceinline__ void g_load_stage(const __half* __restrict__ A,
                                             const __half* __restrict__ Bt,
                                             uint32_t sA, uint32_t sB,
                                             int slot, int kc, int bm, int bn, int tid) {
    const __half* srcA = A  + (size_t)bm * DIN + kc * 64;
    const __half* srcB = Bt + (size_t)bn * DIN + kc * 64;
    const uint32_t dA = sA + slot * A_STG * 2;
    const uint32_t dB = sB + slot * B_STG * 2;
    #pragma unroll
    for (int i = 0; i < 8; i++) {
        int idx = tid + i * 256;
        int row = idx >> 3, c8 = idx & 7;
        cp_async16(dA + (row * HST + c8 * 8) * 2, srcA + (size_t)row * DIN + c8 * 8);
    }
    #pragma unroll
    for (int i = 0; i < 4; i++) {
        int idx = tid + i * 256;
        int row = idx >> 3, c8 = idx & 7;
        cp_async16(dB + (row * HST + c8 * 8) * 2, srcB + (size_t)row * DIN + c8 * 8);
    }
}

template<int EPI>
__device__ __forceinline__ void gemm_tile_body(const __half* __restrict__ A,
                                               const __half* __restrict__ Bt,
                                               void* __restrict__ Cv, float escale) {
    extern __shared__ __half hsmem[];
    const uint32_t sAu = smem_u32(hsmem);
    const uint32_t sBu = sAu + GSTAGES * A_STG * 2;

    const int tid  = threadIdx.x;
    const int lane = tid & 31;
    const int wid  = tid >> 5;
    const int wm   = wid >> 1;
    const int wn   = wid & 1;
    const int bm   = blockIdx.y * 256;
    const int bn   = blockIdx.x * 128;
    const int gr   = lane >> 2;
    const int c2   = (lane & 3) * 2;

    const int lA_row = lane & 15;
    const int lA_col = (lane >> 4) * 8;
    const int lB_row = (lane & 7) + ((lane >> 4) & 1) * 8;
    const int lB_col = ((lane >> 3) & 1) * 8;

    float acc[32][4] = {};

    const int NKC = DIN / 64;    // 16 chunks

    g_load_stage(A, Bt, sAu, sBu, 0, 0, bm, bn, tid); cp_commit();
    g_load_stage(A, Bt, sAu, sBu, 1, 1, bm, bn, tid); cp_commit();
    g_load_stage(A, Bt, sAu, sBu, 2, 2, bm, bn, tid); cp_commit();

    for (int kc = 0; kc < NKC; kc++) {
        cp_wait<2>();                    // chunk kc arrived (locally)
        __syncthreads();                 // visible to all; slot (kc+3)&3 free
        if (kc + 3 < NKC)
            g_load_stage(A, Bt, sAu, sBu, (kc + 3) & 3, kc + 3, bm, bn, tid);
        cp_commit();                     // unconditional: keeps group count aligned

        const uint32_t cA = sAu + (kc & 3) * A_STG * 2;
        const uint32_t cB = sBu + (kc & 3) * B_STG * 2;

        // register double-buffered fragments
        uint32_t a[2][4][4], b[2][4][4];
        #pragma unroll
        for (int mi = 0; mi < 4; mi++)
            ldsm_x4(a[0][mi], cA + (((wm * 64 + mi * 16 + lA_row) * HST + lA_col) << 1));
        #pragma unroll
        for (int jj = 0; jj < 4; jj++)
            ldsm_x4(b[0][jj], cB + (((wn * 64 + jj * 16 + lB_row) * HST + lB_col) << 1));

        #pragma unroll
        for (int ks = 0; ks < 4; ks++) {
            const int cb = ks & 1, nb = cb ^ 1;
            if (ks < 3) {
                const int k1 = (ks + 1) * 16;
                #pragma unroll
                for (int mi = 0; mi < 4; mi++)
                    ldsm_x4(a[nb][mi], cA + (((wm * 64 + mi * 16 + lA_row) * HST + k1 + lA_col) << 1));
                #pragma unroll
                for (int jj = 0; jj < 4; jj++)
                    ldsm_x4(b[nb][jj], cB + (((wn * 64 + jj * 16 + lB_row) * HST + k1 + lB_col) << 1));
            }
            #pragma unroll
            for (int mi = 0; mi < 4; mi++)
                #pragma unroll
                for (int j = 0; j < 8; j++)
                    mma_f16(acc[mi*8+j], a[cb][mi], &b[cb][j >> 1][(j & 1) * 2]);
        }
    }

    #pragma unroll
    for (int mi = 0; mi < 4; mi++) {
        const int row = bm + wm * 64 + mi * 16 + gr;
        #pragma unroll
        for (int j = 0; j < 8; j++) {
            const int col = bn + wn * 64 + j * 8 + c2;
            float v0 = acc[mi*8+j][0], v1 = acc[mi*8+j][1];
            float v2 = acc[mi*8+j][2], v3 = acc[mi*8+j][3];
            if (EPI == 0) {
                float* C = (float*)Cv;
                *(float2*)(C + (size_t)row * DOUT + col)       = make_float2(v0, v1);
                *(float2*)(C + (size_t)(row + 8) * DOUT + col) = make_float2(v2, v3);
            } else if (EPI == 1) {
                __half* C = (__half*)Cv;
                *(__half2*)(C + (size_t)row * DOUT + col)       = __floats2half2_rn(v0*escale, v1*escale);
                *(__half2*)(C + (size_t)(row + 8) * DOUT + col) = __floats2half2_rn(v2*escale, v3*escale);
            } else {
                __half* C = (__half*)Cv;
                const int b0i = row >> 11,     s0 = row & 2047;
                const int b1i = (row+8) >> 11, s1 = (row+8) & 2047;
                #pragma unroll
                for (int q = 0; q < 2; q++) {
                    const int cc = col + q;
                    const size_t base = ((size_t)(cc >> 6) * HD + (cc & 63)) * SEQ;
                    C[(size_t)b0i * NH * HD * SEQ + base + s0] = __float2half_rn(q ? v1 : v0);
                    C[(size_t)b1i * NH * HD * SEQ + base + s1] = __float2half_rn(q ? v3 : v2);
                }
            }
        }
    }
}

#define QSCALE (0.125f * 1.4426950408889634f)   // 1/sqrt(64) * log2(e)

__global__ void __launch_bounds__(256) qkv_mma_kernel() {
    if (blockIdx.z == 0)      gemm_tile_body<1>(g_Xh, g_Wth[0], g_Qh, QSCALE);
    else if (blockIdx.z == 1) gemm_tile_body<1>(g_Xh, g_Wth[1], g_Kh, 1.0f);
    else                      gemm_tile_body<2>(g_Xh, g_Wth[2], g_Vth, 1.0f);
}

__global__ void __launch_bounds__(256) out_mma_kernel(float* __restrict__ out) {
    gemm_tile_body<0>(g_Ah, g_Wth[3], out, 1.0f);
}

// ---------------------------------------------------------------------------
// fp16 tensor-core causal flash attention: fixed-reference base-2 softmax,
// fp16x2 exp, l via ones-rows MMA, paired q-tiles.
// NEW: 4-slot K/V ring in pair-parity — TWO 64-key blocks per cp_wait +
// __syncthreads (barrier count halved, registers unchanged).
// ---------------------------------------------------------------------------
#define HSTA 72
#define KBUF_K (64*HSTA)
#define KBUF_V (80*HSTA)
#define ATTN_SMEM ((4*KBUF_K + 4*KBUF_V)*2)   // 82944 bytes (2 CTAs/SM)

__device__ __forceinline__ void attn_load(const __half* __restrict__ Kg,
                                          const __half* __restrict__ Vt,
                                          uint32_t sKu, uint32_t sVu,
                                          int slot, int kbase, int tid) {
    const uint32_t dK = sKu + slot * KBUF_K * 2;
    const uint32_t dV = sVu + slot * KBUF_V * 2;
    #pragma unroll
    for (int i = 0; i < 2; i++) {
        int idx = tid + i * 256;
        int row = idx >> 3, c8 = idx & 7;
        uint32_t off = (row * HSTA + c8 * 8) * 2;
        cp_async16(dK + off, Kg + (size_t)(kbase + row) * DOUT + c8 * 8);
        cp_async16(dV + off, Vt + (size_t)row * SEQ + kbase + c8 * 8);
    }
}

__global__ void __launch_bounds__(256, 2) attn_f16_kernel() {
    extern __shared__ __half hsmem[];
    const uint32_t sKu = smem_u32(hsmem);
    const uint32_t sVu = sKu + 4 * KBUF_K * 2;

    const int h   = blockIdx.y;
    const int b   = blockIdx.z;
    const int tid = threadIdx.x;
    const int lane = tid & 31;
    const int wid  = tid >> 5;
    const int gr = lane >> 2, c2 = (lane & 3) * 2;

    const int lB_row = (lane & 7) + ((lane >> 4) & 1) * 8;
    const int lB_col = ((lane >> 3) & 1) * 8;

    const size_t rowbase = (size_t)b * SEQ;
    const int colbase = h * HD;
    const __half* Kg = g_Kh + rowbase * DOUT + colbase;
    const __half* Vt = g_Vth + (size_t)(b * NH + h) * HD * SEQ;

    const int wrow = wid * 16;

    // init constant rows 64-79 of each of the 4 V slots: 64-71 = 1.0, 72-79 = 0.
    for (int i = tid; i < 4 * 16 * (HSTA/2); i += 256) {
        const int slot = i / (16 * (HSTA/2));
        const int rem  = i % (16 * (HSTA/2));
        const int r = rem / (HSTA/2), c = rem % (HSTA/2);
        uint32_t val = (r < 8) ? 0x3C003C00u : 0u;
        *(uint32_t*)(hsmem + 4*KBUF_K + slot*KBUF_V + (64 + r)*HSTA + c*2) = val;
    }

    #pragma unroll
    for (int seg = 0; seg < 2; seg++) {
        const int qt = seg == 0 ? (15 - (int)blockIdx.x) : (int)blockIdx.x;
        const int qbase = qt * 128;
        const int npairs = qt + 1;       // nkb = 2*qt+2 blocks = qt+1 pairs
        const int qg0 = qbase + wrow + gr;
        const int qg1 = qg0 + 8;

        // preload Q fragments (already scaled by 0.125*log2e)
        uint32_t qf[4][4];
        {
            const __half* Qg = g_Qh + (rowbase + qbase + wrow + gr) * DOUT + colbase + c2;
            #pragma unroll
            for (int ks = 0; ks < 4; ks++) {
                const __half* qp = Qg + ks * 16;
                qf[ks][0] = *(const uint32_t*)(qp);
                qf[ks][1] = *(const uint32_t*)(qp + 8 * DOUT);
                qf[ks][2] = *(const uint32_t*)(qp + 8);
                qf[ks][3] = *(const uint32_t*)(qp + 8 * DOUT + 8);
            }
        }

        float o[9][4] = {};   // o[0..7] = output dims; o[8] = row-sum l

        __syncthreads();                 // slots free from previous segment
        attn_load(Kg, Vt, sKu, sVu, 0, 0, tid);
        attn_load(Kg, Vt, sKu, sVu, 1, 64, tid);
        cp_commit();

        for (int p = 0; p < npairs; p++) {
            cp_wait<0>();                // pair p resident (locally)
            __syncthreads();             // visible; other slot-pair free (pair p-1 done)
            if (p + 1 < npairs) {
                const int sl = ((p + 1) & 1) * 2;
                attn_load(Kg, Vt, sKu, sVu, sl,     (2*p + 2) * 64, tid);
                attn_load(Kg, Vt, sKu, sVu, sl + 1, (2*p + 3) * 64, tid);
            }
            cp_commit();                 // overlaps with pair-p compute

            #pragma unroll
            for (int sub = 0; sub < 2; sub++) {
                const int kb = 2*p + sub;
                const int slot = (p & 1) * 2 + sub;
                const uint32_t cK = sKu + slot * KBUF_K * 2;
                const uint32_t cV = sVu + slot * KBUF_V * 2;
                const int kbase = kb * 64;

                // S = Q K^T  (base-2 log scale)
                float s[8][4] = {};
                #pragma unroll
                for (int ks = 0; ks < 4; ks++) {
                    const int k0 = ks * 16;
                    uint32_t bk[4][4];
                    #pragma unroll
                    for (int jj = 0; jj < 4; jj++)
                        ldsm_x4(bk[jj], cK + (((jj * 16 + lB_row) * HSTA + k0 + lB_col) << 1));
                    #pragma unroll
                    for (int j = 0; j < 8; j++)
                        mma_f16(s[j], qf[ks], &bk[j >> 1][(j & 1) * 2]);
                }

                // causal mask only near the diagonal
                if (kbase + 63 > qbase + wrow) {
                    #pragma unroll
                    for (int j = 0; j < 8; j++) {
                        const int col0 = kbase + j * 8 + c2;
                        if (col0     > qg0) s[j][0] = -64.f;
                        if (col0 + 1 > qg0) s[j][1] = -64.f;
                        if (col0     > qg1) s[j][2] = -64.f;
                        if (col0 + 1 > qg1) s[j][3] = -64.f;
                    }
                }

                // P = exp2(s) in fp16x2, directly in A-fragment order
                uint32_t pf[8][2];
                #pragma unroll
                for (int j = 0; j < 8; j++) {
                    pf[j][0] = ex2h2(packh2(s[j][0], s[j][1]));
                    pf[j][1] = ex2h2(packh2(s[j][2], s[j][3]));
                }

                // O += P V ; extra n-tile (ones rows) accumulates l into o[8]
                #pragma unroll
                for (int t = 0; t < 4; t++) {
                    const int k0 = t * 16;
                    uint32_t ap[4] = { pf[2*t][0], pf[2*t][1], pf[2*t+1][0], pf[2*t+1][1] };
                    uint32_t bv[5][4];
                    #pragma unroll
                    for (int jj = 0; jj < 5; jj++)
                        ldsm_x4(bv[jj], cV + (((jj * 16 + lB_row) * HSTA + k0 + lB_col) << 1));
                    #pragma unroll
                    for (int j = 0; j < 9; j++)
                        mma_f16(o[j], ap, &bv[j >> 1][(j & 1) * 2]);
                }
            }
        }

        // normalize by l + fp16 store
        const float inv0 = 1.f / o[8][0];
        const float inv1 = 1.f / o[8][2];
        #pragma unroll
        for (int j = 0; j < 8; j++) {
            const int col = colbase + j * 8 + c2;
            *(__half2*)&g_Ah[(rowbase + qbase + wrow + gr) * DOUT + col] =
                __floats2half2_rn(o[j][0] * inv0, o[j][1] * inv0);
            *(__half2*)&g_Ah[(rowbase + qbase + wrow + gr + 8) * DOUT + col] =
                __floats2half2_rn(o[j][2] * inv1, o[j][3] * inv1);
        }
    }
}

// ---------------------------------------------------------------------------
extern "C" void kernel_launch(void* const* d_in, const int* in_sizes, int n_in,
                              void* d_out, int out_size) {
    (void)in_sizes; (void)n_in; (void)out_size;
    const float* x    = (const float*)d_in[0];
    const float* Wq   = (const float*)d_in[1];
    const float* Wk   = (const float*)d_in[2];
    const float* Wv   = (const float*)d_in[3];
    const float* Wout = (const float*)d_in[4];
    float* out = (float*)d_out;

    static bool attr_set = false;
    if (!attr_set) {
        cudaFuncSetAttribute(attn_f16_kernel,
                             cudaFuncAttributeMaxDynamicSharedMemorySize, ATTN_SMEM);
        cudaFuncSetAttribute(qkv_mma_kernel,
                             cudaFuncAttributeMaxDynamicSharedMemorySize, GEMM_SMEM);
        cudaFuncSetAttribute(out_mma_kernel,
                             cudaFuncAttributeMaxDynamicSharedMemorySize, GEMM_SMEM);
        attr_set = true;
    }

    prep_kernel<<<dim3(32, 32, 5), dim3(32, 8)>>>(x, Wq, Wk, Wv, Wout);

    qkv_mma_kernel<<<dim3(DOUT/128, MTOT/256, 3), 256, GEMM_SMEM>>>();

    attn_f16_kernel<<<dim3(SEQ/256, NH, BATCH), 256, ATTN_SMEM>>>();

    out_mma_kernel<<<dim3(DOUT/128, MTOT/256), 256, GEMM_SMEM>>>(out);
}

// round 15
// speedup vs baseline: 1.0505x; 1.0128x over previous
#include <cuda_runtime.h>
#include <cuda_fp16.h>
#include <math.h>
#include <stdint.h>

#define BATCH 2
#define SEQ   2048
#define DIN   1024
#define DOUT  1024
#define NH    16
#define HD    64
#define MTOT  (BATCH*SEQ)   // 4096

// ---------------------------------------------------------------------------
// scratch (no cudaMalloc allowed)
// ---------------------------------------------------------------------------
__device__ __half g_Xh[MTOT*DIN];            // x in fp16
__device__ __half g_Wth[4][DIN*DOUT];        // W^T [n][k] fp16 (q,k,v,out)
__device__ __half g_Qh[MTOT*DOUT];           // pre-scaled by 0.125*log2(e)
__device__ __half g_Kh[MTOT*DOUT];
__device__ __half g_Vth[BATCH*NH*HD*SEQ];    // V transposed [b,h,d,s]
__device__ __half g_Ah[MTOT*DOUT];           // attention output

// ---------------------------------------------------------------------------
// helpers
// ---------------------------------------------------------------------------
__device__ __forceinline__ uint32_t smem_u32(const void* p) {
    return (uint32_t)__cvta_generic_to_shared(p);
}

__device__ __forceinline__ void cp_async16(uint32_t dst, const void* src) {
    asm volatile("cp.async.cg.shared.global [%0], [%1], 16;" :: "r"(dst), "l"(src) : "memory");
}
__device__ __forceinline__ void cp_commit() {
    asm volatile("cp.async.commit_group;" ::: "memory");
}
template<int N>
__device__ __forceinline__ void cp_wait() {
    asm volatile("cp.async.wait_group %0;" :: "n"(N) : "memory");
}

__device__ __forceinline__ uint32_t packh2(float a, float b) {
    __half2 h = __floats2half2_rn(a, b);
    return *(uint32_t*)&h;
}

__device__ __forceinline__ uint32_t ex2h2(uint32_t x) {
    uint32_t y; asm("ex2.approx.f16x2 %0, %1;" : "=r"(y) : "r"(x)); return y;
}

// m16n8k16 fp16 HMMA, row.col, fp32 accumulate
__device__ __forceinline__ void mma_f16(float* d, const uint32_t* a, const uint32_t* b) {
    asm volatile(
        "mma.sync.aligned.m16n8k16.row.col.f32.f16.f16.f32 "
        "{%0,%1,%2,%3}, {%4,%5,%6,%7}, {%8,%9}, {%0,%1,%2,%3};"
        : "+f"(d[0]), "+f"(d[1]), "+f"(d[2]), "+f"(d[3])
        : "r"(a[0]), "r"(a[1]), "r"(a[2]), "r"(a[3]), "r"(b[0]), "r"(b[1]));
}

__device__ __forceinline__ void ldsm_x4(uint32_t* r, uint32_t addr) {
    asm volatile("ldmatrix.sync.aligned.m8n8.x4.shared.b16 {%0,%1,%2,%3}, [%4];"
        : "=r"(r[0]), "=r"(r[1]), "=r"(r[2]), "=r"(r[3]) : "r"(addr));
}

// ---------------------------------------------------------------------------
// prep kernel: z<4 -> transpose+convert W[z]; z==4 -> convert x.
// ---------------------------------------------------------------------------
__global__ void prep_kernel(const float* __restrict__ x,
                            const float* __restrict__ Wq,
                            const float* __restrict__ Wk,
                            const float* __restrict__ Wv,
                            const float* __restrict__ Wo) {
    const int z = blockIdx.z;
    const int tx = threadIdx.x, ty = threadIdx.y;
    if (z == 4) {
        const int bid = blockIdx.y * 32 + blockIdx.x;
        const int tid = ty * 32 + tx;
        #pragma unroll
        for (int i = 0; i < 4; i++) {
            int idx = bid * 1024 + i * 256 + tid;
            float4 v = ((const float4*)x)[idx];
            __half2 h0 = __floats2half2_rn(v.x, v.y);
            __half2 h1 = __floats2half2_rn(v.z, v.w);
            uint2 u;
            u.x = *(uint32_t*)&h0;
            u.y = *(uint32_t*)&h1;
            ((uint2*)g_Xh)[idx] = u;
        }
        return;
    }
    __shared__ float t[32][33];
    const float* W = (z == 0) ? Wq : (z == 1) ? Wk : (z == 2) ? Wv : Wo;
    __half* out = g_Wth[z];
    const int n0 = blockIdx.x * 32, k0 = blockIdx.y * 32;
    #pragma unroll
    for (int i = 0; i < 4; i++)
        t[ty + 8*i][tx] = W[(size_t)(k0 + ty + 8*i) * DOUT + n0 + tx];
    __syncthreads();
    #pragma unroll
    for (int i = 0; i < 4; i++)
        out[(size_t)(n0 + ty + 8*i) * DIN + k0 + tx] = __float2half_rn(t[tx][ty + 8*i]);
}

// ---------------------------------------------------------------------------
// fp16 HMMA GEMM (R12/R14 config): 256x128 CTA tile, warp tile 64x64, BK=64,
// 4-stage cp.async pipeline, one __syncthreads per chunk, register
// double-buffered ldmatrix fragments.
// ---------------------------------------------------------------------------
#define HST 72
#define A_STG (256*HST)
#define B_STG (128*HST)
#define GSTAGES 4
#define GEMM_SMEM (GSTAGES*(A_STG+B_STG)*2)   // 221184 bytes

__device__ __forceinline__ void g_load_stage(const __half* __restrict__ A,
                                             const __half* __restrict__ Bt,
                                             uint32_t sA, uint32_t sB,
                                             int slot, int kc, int bm, int bn, int tid) {
    const __half* srcA = A  + (size_t)bm * DIN + kc * 64;
    const __half* srcB = Bt + (size_t)bn * DIN + kc * 64;
    const uint32_t dA = sA + slot * A_STG * 2;
    const uint32_t dB = sB + slot * B_STG * 2;
    #pragma unroll
    for (int i = 0; i < 8; i++) {
        int idx = tid + i * 256;
        int row = idx >> 3, c8 = idx & 7;
        cp_async16(dA + (row * HST + c8 * 8) * 2, srcA + (size_t)row * DIN + c8 * 8);
    }
    #pragma unroll
    for (int i = 0; i < 4; i++) {
        int idx = tid + i * 256;
        int row = idx >> 3, c8 = idx & 7;
        cp_async16(dB + (row * HST + c8 * 8) * 2, srcB + (size_t)row * DIN + c8 * 8);
    }
}

template<int EPI>
__device__ __forceinline__ void gemm_tile_body(const __half* __restrict__ A,
                                               const __half* __restrict__ Bt,
                                               void* __restrict__ Cv, float escale) {
    extern __shared__ __half hsmem[];
    const uint32_t sAu = smem_u32(hsmem);
    const uint32_t sBu = sAu + GSTAGES * A_STG * 2;

    const int tid  = threadIdx.x;
    const int lane = tid & 31;
    const int wid  = tid >> 5;
    const int wm   = wid >> 1;
    const int wn   = wid & 1;
    const int bm   = blockIdx.y * 256;
    const int bn   = blockIdx.x * 128;
    const int gr   = lane >> 2;
    const int c2   = (lane & 3) * 2;

    const int lA_row = lane & 15;
    const int lA_col = (lane >> 4) * 8;
    const int lB_row = (lane & 7) + ((lane >> 4) & 1) * 8;
    const int lB_col = ((lane >> 3) & 1) * 8;

    float acc[32][4] = {};

    const int NKC = DIN / 64;    // 16 chunks

    g_load_stage(A, Bt, sAu, sBu, 0, 0, bm, bn, tid); cp_commit();
    g_load_stage(A, Bt, sAu, sBu, 1, 1, bm, bn, tid); cp_commit();
    g_load_stage(A, Bt, sAu, sBu, 2, 2, bm, bn, tid); cp_commit();

    for (int kc = 0; kc < NKC; kc++) {
        cp_wait<2>();                    // chunk kc arrived (locally)
        __syncthreads();                 // visible to all; slot (kc+3)&3 free
        if (kc + 3 < NKC)
            g_load_stage(A, Bt, sAu, sBu, (kc + 3) & 3, kc + 3, bm, bn, tid);
        cp_commit();                     // unconditional: keeps group count aligned

        const uint32_t cA = sAu + (kc & 3) * A_STG * 2;
        const uint32_t cB = sBu + (kc & 3) * B_STG * 2;

        // register double-buffered fragments
        uint32_t a[2][4][4], b[2][4][4];
        #pragma unroll
        for (int mi = 0; mi < 4; mi++)
            ldsm_x4(a[0][mi], cA + (((wm * 64 + mi * 16 + lA_row) * HST + lA_col) << 1));
        #pragma unroll
        for (int jj = 0; jj < 4; jj++)
            ldsm_x4(b[0][jj], cB + (((wn * 64 + jj * 16 + lB_row) * HST + lB_col) << 1));

        #pragma unroll
        for (int ks = 0; ks < 4; ks++) {
            const int cb = ks & 1, nb = cb ^ 1;
            if (ks < 3) {
                const int k1 = (ks + 1) * 16;
                #pragma unroll
                for (int mi = 0; mi < 4; mi++)
                    ldsm_x4(a[nb][mi], cA + (((wm * 64 + mi * 16 + lA_row) * HST + k1 + lA_col) << 1));
                #pragma unroll
                for (int jj = 0; jj < 4; jj++)
                    ldsm_x4(b[nb][jj], cB + (((wn * 64 + jj * 16 + lB_row) * HST + k1 + lB_col) << 1));
            }
            #pragma unroll
            for (int mi = 0; mi < 4; mi++)
                #pragma unroll
                for (int j = 0; j < 8; j++)
                    mma_f16(acc[mi*8+j], a[cb][mi], &b[cb][j >> 1][(j & 1) * 2]);
        }
    }

    #pragma unroll
    for (int mi = 0; mi < 4; mi++) {
        const int row = bm + wm * 64 + mi * 16 + gr;
        #pragma unroll
        for (int j = 0; j < 8; j++) {
            const int col = bn + wn * 64 + j * 8 + c2;
            float v0 = acc[mi*8+j][0], v1 = acc[mi*8+j][1];
            float v2 = acc[mi*8+j][2], v3 = acc[mi*8+j][3];
            if (EPI == 0) {
                float* C = (float*)Cv;
                *(float2*)(C + (size_t)row * DOUT + col)       = make_float2(v0, v1);
                *(float2*)(C + (size_t)(row + 8) * DOUT + col) = make_float2(v2, v3);
            } else if (EPI == 1) {
                __half* C = (__half*)Cv;
                *(__half2*)(C + (size_t)row * DOUT + col)       = __floats2half2_rn(v0*escale, v1*escale);
                *(__half2*)(C + (size_t)(row + 8) * DOUT + col) = __floats2half2_rn(v2*escale, v3*escale);
            } else {
                __half* C = (__half*)Cv;
                const int b0i = row >> 11,     s0 = row & 2047;
                const int b1i = (row+8) >> 11, s1 = (row+8) & 2047;
                #pragma unroll
                for (int q = 0; q < 2; q++) {
                    const int cc = col + q;
                    const size_t base = ((size_t)(cc >> 6) * HD + (cc & 63)) * SEQ;
                    C[(size_t)b0i * NH * HD * SEQ + base + s0] = __float2half_rn(q ? v1 : v0);
                    C[(size_t)b1i * NH * HD * SEQ + base + s1] = __float2half_rn(q ? v3 : v2);
                }
            }
        }
    }
}

#define QSCALE (0.125f * 1.4426950408889634f)   // 1/sqrt(64) * log2(e)

__global__ void __launch_bounds__(256) qkv_mma_kernel() {
    if (blockIdx.z == 0)      gemm_tile_body<1>(g_Xh, g_Wth[0], g_Qh, QSCALE);
    else if (blockIdx.z == 1) gemm_tile_body<1>(g_Xh, g_Wth[1], g_Kh, 1.0f);
    else                      gemm_tile_body<2>(g_Xh, g_Wth[2], g_Vth, 1.0f);
}

__global__ void __launch_bounds__(256) out_mma_kernel(float* __restrict__ out) {
    gemm_tile_body<0>(g_Ah, g_Wth[3], out, 1.0f);
}

// ---------------------------------------------------------------------------
// fp16 tensor-core causal flash attention: fixed-reference base-2 softmax,
// fp16x2 exp, l via ones-rows MMA, paired q-tiles, 4-slot pair-parity ring.
// NEW: 4 warps x 32 q-rows (two m16 tiles per warp) — K/V fragments loaded
// once per warp feed both m-tiles, halving smem ldmatrix traffic per MAC.
// 128 threads, 2 CTAs/SM.
// ---------------------------------------------------------------------------
#define HSTA 72
#define KBUF_K (64*HSTA)
#define KBUF_V (80*HSTA)
#define ATTN_SMEM ((4*KBUF_K + 4*KBUF_V)*2)   // 82944 bytes

__device__ __forceinline__ void attn_load(const __half* __restrict__ Kg,
                                          const __half* __restrict__ Vt,
                                          uint32_t sKu, uint32_t sVu,
                                          int slot, int kbase, int tid) {
    const uint32_t dK = sKu + slot * KBUF_K * 2;
    const uint32_t dV = sVu + slot * KBUF_V * 2;
    #pragma unroll
    for (int i = 0; i < 4; i++) {
        int idx = tid + i * 128;         // 0..511 = 64 rows x 8 chunks
        int row = idx >> 3, c8 = idx & 7;
        uint32_t off = (row * HSTA + c8 * 8) * 2;
        cp_async16(dK + off, Kg + (size_t)(kbase + row) * DOUT + c8 * 8);
        cp_async16(dV + off, Vt + (size_t)row * SEQ + kbase + c8 * 8);
    }
}

__global__ void __launch_bounds__(128, 2) attn_f16_kernel() {
    extern __shared__ __half hsmem[];
    const uint32_t sKu = smem_u32(hsmem);
    const uint32_t sVu = sKu + 4 * KBUF_K * 2;

    const int h   = blockIdx.y;
    const int b   = blockIdx.z;
    const int tid = threadIdx.x;
    const int lane = tid & 31;
    const int wid  = tid >> 5;          // 0..3
    const int gr = lane >> 2, c2 = (lane & 3) * 2;

    const int lB_row = (lane & 7) + ((lane >> 4) & 1) * 8;
    const int lB_col = ((lane >> 3) & 1) * 8;

    const size_t rowbase = (size_t)b * SEQ;
    const int colbase = h * HD;
    const __half* Kg = g_Kh + rowbase * DOUT + colbase;
    const __half* Vt = g_Vth + (size_t)(b * NH + h) * HD * SEQ;

    const int wrow = wid * 32;          // warp covers rows wrow..wrow+31 (2 m-tiles)

    // init constant rows 64-79 of each of the 4 V slots: 64-71 = 1.0, 72-79 = 0.
    for (int i = tid; i < 4 * 16 * (HSTA/2); i += 128) {
        const int slot = i / (16 * (HSTA/2));
        const int rem  = i % (16 * (HSTA/2));
        const int r = rem / (HSTA/2), c = rem % (HSTA/2);
        uint32_t val = (r < 8) ? 0x3C003C00u : 0u;
        *(uint32_t*)(hsmem + 4*KBUF_K + slot*KBUF_V + (64 + r)*HSTA + c*2) = val;
    }

    #pragma unroll
    for (int seg = 0; seg < 2; seg++) {
        const int qt = seg == 0 ? (15 - (int)blockIdx.x) : (int)blockIdx.x;
        const int qbase = qt * 128;
        const int npairs = qt + 1;       // nkb = 2*qt+2 blocks = qt+1 pairs
        // per-m-tile row bases for causal masking
        const int qg00 = qbase + wrow + gr;        // m-tile 0, acc rows gr / gr+8
        const int qg01 = qg00 + 8;
        const int qg10 = qg00 + 16;                // m-tile 1
        const int qg11 = qg00 + 24;

        // preload Q fragments for both m-tiles (already scaled by 0.125*log2e)
        uint32_t qf[2][4][4];
        #pragma unroll
        for (int m = 0; m < 2; m++) {
            const __half* Qg = g_Qh + (rowbase + qbase + wrow + m * 16 + gr) * DOUT + colbase + c2;
            #pragma unroll
            for (int ks = 0; ks < 4; ks++) {
                const __half* qp = Qg + ks * 16;
                qf[m][ks][0] = *(const uint32_t*)(qp);
                qf[m][ks][1] = *(const uint32_t*)(qp + 8 * DOUT);
                qf[m][ks][2] = *(const uint32_t*)(qp + 8);
                qf[m][ks][3] = *(const uint32_t*)(qp + 8 * DOUT + 8);
            }
        }

        float o[2][9][4] = {};   // per m-tile: o[.][0..7] dims, o[.][8] row-sum l

        __syncthreads();                 // slots free from previous segment
        attn_load(Kg, Vt, sKu, sVu, 0, 0, tid);
        attn_load(Kg, Vt, sKu, sVu, 1, 64, tid);
        cp_commit();

        for (int p = 0; p < npairs; p++) {
            cp_wait<0>();                // pair p resident (locally)
            __syncthreads();             // visible; other slot-pair free
            if (p + 1 < npairs) {
                const int sl = ((p + 1) & 1) * 2;
                attn_load(Kg, Vt, sKu, sVu, sl,     (2*p + 2) * 64, tid);
                attn_load(Kg, Vt, sKu, sVu, sl + 1, (2*p + 3) * 64, tid);
            }
            cp_commit();                 // overlaps with pair-p compute

            #pragma unroll
            for (int sub = 0; sub < 2; sub++) {
                const int kb = 2*p + sub;
                const int slot = (p & 1) * 2 + sub;
                const uint32_t cK = sKu + slot * KBUF_K * 2;
                const uint32_t cV = sVu + slot * KBUF_V * 2;
                const int kbase = kb * 64;

                // S = Q K^T for both m-tiles; bk loaded once per ks
                float s[2][8][4] = {};
                #pragma unroll
                for (int ks = 0; ks < 4; ks++) {
                    const int k0 = ks * 16;
                    uint32_t bk[4][4];
                    #pragma unroll
                    for (int jj = 0; jj < 4; jj++)
                        ldsm_x4(bk[jj], cK + (((jj * 16 + lB_row) * HSTA + k0 + lB_col) << 1));
                    #pragma unroll
                    for (int j = 0; j < 8; j++) {
                        const uint32_t* bf = &bk[j >> 1][(j & 1) * 2];
                        mma_f16(s[0][j], qf[0][ks], bf);
                        mma_f16(s[1][j], qf[1][ks], bf);
                    }
                }

                // causal mask only near the diagonal (warp min row = wrow)
                if (kbase + 63 > qbase + wrow) {
                    #pragma unroll
                    for (int j = 0; j < 8; j++) {
                        const int col0 = kbase + j * 8 + c2;
                        if (col0     > qg00) s[0][j][0] = -64.f;
                        if (col0 + 1 > qg00) s[0][j][1] = -64.f;
                        if (col0     > qg01) s[0][j][2] = -64.f;
                        if (col0 + 1 > qg01) s[0][j][3] = -64.f;
                        if (col0     > qg10) s[1][j][0] = -64.f;
                        if (col0 + 1 > qg10) s[1][j][1] = -64.f;
                        if (col0     > qg11) s[1][j][2] = -64.f;
                        if (col0 + 1 > qg11) s[1][j][3] = -64.f;
                    }
                }

                // P = exp2(s) in fp16x2, A-fragment order, both m-tiles
                uint32_t pf[2][8][2];
                #pragma unroll
                for (int m = 0; m < 2; m++)
                    #pragma unroll
                    for (int j = 0; j < 8; j++) {
                        pf[m][j][0] = ex2h2(packh2(s[m][j][0], s[m][j][1]));
                        pf[m][j][1] = ex2h2(packh2(s[m][j][2], s[m][j][3]));
                    }

                // O += P V ; bv loaded once per t feeds both m-tiles;
                // extra n-tile (ones rows) accumulates l into o[.][8]
                #pragma unroll
                for (int t = 0; t < 4; t++) {
                    const int k0 = t * 16;
                    uint32_t ap0[4] = { pf[0][2*t][0], pf[0][2*t][1], pf[0][2*t+1][0], pf[0][2*t+1][1] };
                    uint32_t ap1[4] = { pf[1][2*t][0], pf[1][2*t][1], pf[1][2*t+1][0], pf[1][2*t+1][1] };
                    uint32_t bv[5][4];
                    #pragma unroll
                    for (int jj = 0; jj < 5; jj++)
                        ldsm_x4(bv[jj], cV + (((jj * 16 + lB_row) * HSTA + k0 + lB_col) << 1));
                    #pragma unroll
                    for (int j = 0; j < 9; j++) {
                        const uint32_t* bf = &bv[j >> 1][(j & 1) * 2];
                        mma_f16(o[0][j], ap0, bf);
                        mma_f16(o[1][j], ap1, bf);
                    }
                }
            }
        }

        // normalize by l + fp16 store, both m-tiles
        #pragma unroll
        for (int m = 0; m < 2; m++) {
            const float inv0 = 1.f / o[m][8][0];
            const float inv1 = 1.f / o[m][8][2];
            const size_t r0 = rowbase + qbase + wrow + m * 16 + gr;
            #pragma unroll
            for (int j = 0; j < 8; j++) {
                const int col = colbase + j * 8 + c2;
                *(__half2*)&g_Ah[r0 * DOUT + col] =
                    __floats2half2_rn(o[m][j][0] * inv0, o[m][j][1] * inv0);
                *(__half2*)&g_Ah[(r0 + 8) * DOUT + col] =
                    __floats2half2_rn(o[m][j][2] * inv1, o[m][j][3] * inv1);
            }
        }
    }
}

// ---------------------------------------------------------------------------
extern "C" void kernel_launch(void* const* d_in, const int* in_sizes, int n_in,
                              void* d_out, int out_size) {
    (void)in_sizes; (void)n_in; (void)out_size;
    const float* x    = (const float*)d_in[0];
    const float* Wq   = (const float*)d_in[1];
    const float* Wk   = (const float*)d_in[2];
    const float* Wv   = (const float*)d_in[3];
    const float* Wout = (const float*)d_in[4];
    float* out = (float*)d_out;

    static bool attr_set = false;
    if (!attr_set) {
        cudaFuncSetAttribute(attn_f16_kernel,
                             cudaFuncAttributeMaxDynamicSharedMemorySize, ATTN_SMEM);
        cudaFuncSetAttribute(qkv_mma_kernel,
                             cudaFuncAttributeMaxDynamicSharedMemorySize, GEMM_SMEM);
        cudaFuncSetAttribute(out_mma_kernel,
                             cudaFuncAttributeMaxDynamicSharedMemorySize, GEMM_SMEM);
        attr_set = true;
    }

    prep_kernel<<<dim3(32, 32, 5), dim3(32, 8)>>>(x, Wq, Wk, Wv, Wout);

    qkv_mma_kernel<<<dim3(DOUT/128, MTOT/256, 3), 256, GEMM_SMEM>>>();

    attn_f16_kernel<<<dim3(SEQ/256, NH, BATCH), 128, ATTN_SMEM>>>();

    out_mma_kernel<<<dim3(DOUT/128, MTOT/256), 256, GEMM_SMEM>>>(out);
}